// round 1
// baseline (speedup 1.0000x reference)
#include <cuda_runtime.h>
#include <cstdint>

#define SEQ   2048
#define BATCH 4
#define HEADS 16
#define BH    (BATCH*HEADS)   // 64
#define HD    64
#define PAD   72              // smem row stride (floats): 16B-aligned, conflict-light

// ---------------- device globals (no allocs allowed) ----------------
__device__ float g_Wq[64*64], g_Wk[64*64], g_Wv[64*64];
__device__ float g_bq[64],    g_bk[64],    g_bv[64];
__device__ float g_E[64*64],  g_be[64];
__device__ float g_Q[BH*SEQ*HD];
__device__ float g_K[BH*SEQ*HD];
__device__ float g_V[BH*SEQ*HD];

__device__ __forceinline__ float tf32r(float x) {
    uint32_t u;
    asm("cvt.rna.tf32.f32 %0, %1;" : "=r"(u) : "f"(x));
    return __uint_as_float(u);
}

__device__ __forceinline__ void mma8(float* d, const uint32_t* a, uint32_t b0, uint32_t b1) {
    asm volatile(
        "mma.sync.aligned.m16n8k8.row.col.f32.tf32.tf32.f32 "
        "{%0,%1,%2,%3}, {%4,%5,%6,%7}, {%8,%9}, {%0,%1,%2,%3};"
        : "+f"(d[0]), "+f"(d[1]), "+f"(d[2]), "+f"(d[3])
        : "r"(a[0]), "r"(a[1]), "r"(a[2]), "r"(a[3]), "r"(b0), "r"(b1));
}

// ---------------- kernel 1: fuse all weights/biases ----------------
__global__ void precompute_kernel(
    const float* __restrict__ Wi,  const float* __restrict__ bi,
    const float* __restrict__ Wq,  const float* __restrict__ bq,
    const float* __restrict__ Wk,  const float* __restrict__ bk,
    const float* __restrict__ Wv,  const float* __restrict__ bv,
    const float* __restrict__ Wc,  const float* __restrict__ bc,
    const float* __restrict__ Wci, const float* __restrict__ bci,
    const float* __restrict__ Wm,  const float* __restrict__ bm,
    const float* __restrict__ Wmi, const float* __restrict__ bmi)
{
    __shared__ float M1[4096], M2[4096], b1s[64];
    const int tid = threadIdx.x;

    // Fused QKV weights: W' = Wx @ Wi  (row o, col i)
    for (int idx = tid; idx < 4096; idx += 256) {
        int o = idx >> 6, i = idx & 63;
        float aq = 0.f, ak = 0.f, av = 0.f;
        for (int j = 0; j < 64; j++) {
            float wij = Wi[j*64 + i];
            aq += Wq[o*64 + j] * wij;
            ak += Wk[o*64 + j] * wij;
            av += Wv[o*64 + j] * wij;
        }
        g_Wq[idx] = tf32r(aq); g_Wk[idx] = tf32r(ak); g_Wv[idx] = tf32r(av);
    }
    // Fused QKV biases: b' = Wx @ bi + bx  (kept fp32)
    for (int o = tid; o < 64; o += 256) {
        float aq = bq[o], ak = bk[o], av = bv[o];
        for (int j = 0; j < 64; j++) {
            float bij = bi[j];
            aq += Wq[o*64 + j] * bij;
            ak += Wk[o*64 + j] * bij;
            av += Wv[o*64 + j] * bij;
        }
        g_bq[o] = aq; g_bk[o] = ak; g_bv[o] = av;
    }
    // M1 = Wci@Wc, M2 = Wmi@Wm, b1 = Wci@bc + bci
    for (int idx = tid; idx < 4096; idx += 256) {
        int o = idx >> 6, i = idx & 63;
        float a1 = 0.f;
        for (int j = 0; j < 8; j++) a1 += Wci[o*8 + j] * Wc[j*64 + i];
        M1[idx] = a1;
        float a2 = 0.f;
        for (int j = 0; j < 4; j++) a2 += Wmi[o*4 + j] * Wm[j*64 + i];
        M2[idx] = a2;
    }
    for (int o = tid; o < 64; o += 256) {
        float a = bci[o];
        for (int j = 0; j < 8; j++) a += Wci[o*8 + j] * bc[j];
        b1s[o] = a;
    }
    __syncthreads();
    // E = M2 @ M1 (fp32, used in SIMT epilogue); be = M2@b1 + (Wmi@bm + bmi)
    for (int idx = tid; idx < 4096; idx += 256) {
        int o = idx >> 6, i = idx & 63;
        float e = 0.f;
        for (int j = 0; j < 64; j++) e += M2[o*64 + j] * M1[j*64 + i];
        g_E[idx] = e;
    }
    for (int o = tid; o < 64; o += 256) {
        float a = bmi[o];
        for (int j = 0; j < 4; j++)  a += Wmi[o*4 + j] * bm[j];
        for (int j = 0; j < 64; j++) a += M2[o*64 + j] * b1s[j];
        g_be[o] = a;
    }
}

// ---------------- kernel 2: QKV projection (tf32 mma) ----------------
// grid (32 s-tiles, 64 bh), 128 threads. out[s][o] = sum_i x[s][i] * W'[o][i] + b'[o]
__global__ __launch_bounds__(128) void qkv_kernel(const float* __restrict__ x)
{
    extern __shared__ float sm[];
    float* xs = sm;                 // 64 x PAD
    float* wq = sm + 64*PAD;
    float* wk = wq + 64*PAD;
    float* wv = wk + 64*PAD;

    const int s0 = blockIdx.x * 64;
    const int bh = blockIdx.y;
    const int b  = bh >> 4, h = bh & 15;
    const int tid = threadIdx.x;

    const float* xbase = x + ((size_t)(b*SEQ + s0))*1024 + h*64;
    for (int idx = tid; idx < 4096; idx += 128) {
        int r = idx >> 6, c = idx & 63;
        xs[r*PAD + c] = tf32r(xbase[(size_t)r*1024 + c]);
    }
    for (int idx = tid; idx < 4096; idx += 128) {
        int r = idx >> 6, c = idx & 63;
        wq[r*PAD + c] = g_Wq[idx];
        wk[r*PAD + c] = g_Wk[idx];
        wv[r*PAD + c] = g_Wv[idx];
    }
    __syncthreads();

    const int w = tid >> 5, lane = tid & 31, g = lane >> 2, t = lane & 3;
    const int r0 = w*16 + g;

    // A fragments (x rows), register-resident across all 3 matrices
    uint32_t a[8][4];
#pragma unroll
    for (int kk = 0; kk < 8; kk++) {
        int c0 = kk*8 + t;
        a[kk][0] = __float_as_uint(xs[r0*PAD + c0]);
        a[kk][1] = __float_as_uint(xs[(r0+8)*PAD + c0]);
        a[kk][2] = __float_as_uint(xs[r0*PAD + c0 + 4]);
        a[kk][3] = __float_as_uint(xs[(r0+8)*PAD + c0 + 4]);
    }

    float* Wsm[3]        = {wq, wk, wv};
    const float* bias[3] = {g_bq, g_bk, g_bv};
    float* outp[3]       = {g_Q, g_K, g_V};

    for (int mat = 0; mat < 3; mat++) {
        float acc[8][4];
#pragma unroll
        for (int j = 0; j < 8; j++)
#pragma unroll
            for (int q = 0; q < 4; q++) acc[j][q] = 0.f;

        const float* Wp = Wsm[mat];
#pragma unroll
        for (int j = 0; j < 8; j++)
#pragma unroll
            for (int kk = 0; kk < 8; kk++) {
                uint32_t b0 = __float_as_uint(Wp[(8*j + g)*PAD + kk*8 + t]);
                uint32_t b1 = __float_as_uint(Wp[(8*j + g)*PAD + kk*8 + t + 4]);
                mma8(acc[j], a[kk], b0, b1);
            }

        float* op = outp[mat];
        const float* bp = bias[mat];
        const size_t base = (size_t)bh*SEQ + s0;
#pragma unroll
        for (int j = 0; j < 8; j++) {
            int col = 8*j + 2*t;
            float bb0 = bp[col], bb1 = bp[col+1];
            float2 v0 = make_float2(tf32r(acc[j][0] + bb0), tf32r(acc[j][1] + bb1));
            float2 v1 = make_float2(tf32r(acc[j][2] + bb0), tf32r(acc[j][3] + bb1));
            *(float2*)&op[(base + r0    )*64 + col] = v0;
            *(float2*)&op[(base + r0 + 8)*64 + col] = v1;
        }
    }
}

// ---------------- kernel 3: flash attention + fused epilogue ----------------
// grid (32 q-tiles, 64 bh), 128 threads (4 warps, 16 q-rows each). Br=Bc=64.
__global__ __launch_bounds__(128) void attn_kernel(float* __restrict__ out)
{
    extern __shared__ float sm[];
    float* Ks = sm;                 // 64 x PAD  (reused for E in epilogue)
    float* Vs = Ks + 64*PAD;
    float* Ps = Vs + 64*PAD;        // P staging / O staging

    const int q0 = blockIdx.x * 64;
    const int bh = blockIdx.y;
    const int b  = bh >> 4, h = bh & 15;
    const int tid  = threadIdx.x;
    const int w    = tid >> 5, lane = tid & 31, g = lane >> 2, t = lane & 3;
    const int r0   = w*16 + g;      // warp-local row (block rows 16w..16w+15)

    // Q fragments, pre-scaled by 1/sqrt(64) = 0.125 (exact in tf32)
    uint32_t aq[8][4];
    {
        const float* Qp = g_Q + ((size_t)bh*SEQ + q0)*64;
#pragma unroll
        for (int kk = 0; kk < 8; kk++) {
            int c0 = kk*8 + t;
            aq[kk][0] = __float_as_uint(Qp[(r0    )*64 + c0    ] * 0.125f);
            aq[kk][1] = __float_as_uint(Qp[(r0 + 8)*64 + c0    ] * 0.125f);
            aq[kk][2] = __float_as_uint(Qp[(r0    )*64 + c0 + 4] * 0.125f);
            aq[kk][3] = __float_as_uint(Qp[(r0 + 8)*64 + c0 + 4] * 0.125f);
        }
    }

    float oacc[8][4];
#pragma unroll
    for (int j = 0; j < 8; j++)
#pragma unroll
        for (int q = 0; q < 4; q++) oacc[j][q] = 0.f;

    float m_lo = -1e30f, m_hi = -1e30f, l_lo = 0.f, l_hi = 0.f;

    const float* Kp = g_K + (size_t)bh*SEQ*64;
    const float* Vp = g_V + (size_t)bh*SEQ*64;

    for (int kt = 0; kt < SEQ/64; kt++) {
        __syncthreads();   // previous tile fully consumed
        {
            const float4* kb = (const float4*)(Kp + (size_t)kt*64*64);
            const float4* vb = (const float4*)(Vp + (size_t)kt*64*64);
#pragma unroll
            for (int i4 = tid; i4 < 1024; i4 += 128) {
                int r = i4 >> 4, c = (i4 & 15) << 2;
                *(float4*)&Ks[r*PAD + c] = kb[i4];
                *(float4*)&Vs[r*PAD + c] = vb[i4];
            }
        }
        __syncthreads();

        // S = Q K^T (scaled), 16x64 per warp
        float s[8][4];
#pragma unroll
        for (int j = 0; j < 8; j++) {
#pragma unroll
            for (int q = 0; q < 4; q++) s[j][q] = 0.f;
#pragma unroll
            for (int kk = 0; kk < 8; kk++) {
                uint32_t b0 = __float_as_uint(Ks[(8*j + g)*PAD + kk*8 + t]);
                uint32_t b1 = __float_as_uint(Ks[(8*j + g)*PAD + kk*8 + t + 4]);
                mma8(s[j], aq[kk], b0, b1);
            }
        }

        // Online softmax (rows r0, r0+8); reduce across the quad (lanes share a row)
        float tmx_lo = -1e30f, tmx_hi = -1e30f;
#pragma unroll
        for (int j = 0; j < 8; j++) {
            tmx_lo = fmaxf(tmx_lo, fmaxf(s[j][0], s[j][1]));
            tmx_hi = fmaxf(tmx_hi, fmaxf(s[j][2], s[j][3]));
        }
#pragma unroll
        for (int off = 1; off < 4; off <<= 1) {
            tmx_lo = fmaxf(tmx_lo, __shfl_xor_sync(0xffffffffu, tmx_lo, off));
            tmx_hi = fmaxf(tmx_hi, __shfl_xor_sync(0xffffffffu, tmx_hi, off));
        }
        float mn_lo = fmaxf(m_lo, tmx_lo), mn_hi = fmaxf(m_hi, tmx_hi);
        float sc_lo = __expf(m_lo - mn_lo), sc_hi = __expf(m_hi - mn_hi);
        m_lo = mn_lo; m_hi = mn_hi;

        float p[8][4];
        float rs_lo = 0.f, rs_hi = 0.f;
#pragma unroll
        for (int j = 0; j < 8; j++) {
            p[j][0] = __expf(s[j][0] - mn_lo);
            p[j][1] = __expf(s[j][1] - mn_lo);
            p[j][2] = __expf(s[j][2] - mn_hi);
            p[j][3] = __expf(s[j][3] - mn_hi);
            rs_lo += p[j][0] + p[j][1];
            rs_hi += p[j][2] + p[j][3];
        }
#pragma unroll
        for (int off = 1; off < 4; off <<= 1) {
            rs_lo += __shfl_xor_sync(0xffffffffu, rs_lo, off);
            rs_hi += __shfl_xor_sync(0xffffffffu, rs_hi, off);
        }
        l_lo = l_lo * sc_lo + rs_lo;
        l_hi = l_hi * sc_hi + rs_hi;

#pragma unroll
        for (int j = 0; j < 8; j++) {
            oacc[j][0] *= sc_lo; oacc[j][1] *= sc_lo;
            oacc[j][2] *= sc_hi; oacc[j][3] *= sc_hi;
        }

        // Stage P (tf32) in this warp's 16 rows of Ps
#pragma unroll
        for (int j = 0; j < 8; j++) {
            int col = 8*j + 2*t;
            *(float2*)&Ps[(r0    )*PAD + col] = make_float2(tf32r(p[j][0]), tf32r(p[j][1]));
            *(float2*)&Ps[(r0 + 8)*PAD + col] = make_float2(tf32r(p[j][2]), tf32r(p[j][3]));
        }
        __syncwarp();

        // O += P V
#pragma unroll
        for (int kk = 0; kk < 8; kk++) {
            uint32_t pa[4];
            int c0 = kk*8 + t;
            pa[0] = __float_as_uint(Ps[(r0    )*PAD + c0    ]);
            pa[1] = __float_as_uint(Ps[(r0 + 8)*PAD + c0    ]);
            pa[2] = __float_as_uint(Ps[(r0    )*PAD + c0 + 4]);
            pa[3] = __float_as_uint(Ps[(r0 + 8)*PAD + c0 + 4]);
#pragma unroll
            for (int j = 0; j < 8; j++) {
                uint32_t b0 = __float_as_uint(Vs[(kk*8 + t    )*PAD + 8*j + g]);
                uint32_t b1 = __float_as_uint(Vs[(kk*8 + t + 4)*PAD + 8*j + g]);
                mma8(oacc[j], pa, b0, b1);
            }
        }
    }

    // Normalize and stage O into Ps (own-warp rows)
    {
        float il_lo = 1.f / l_lo, il_hi = 1.f / l_hi;
#pragma unroll
        for (int j = 0; j < 8; j++) {
            int col = 8*j + 2*t;
            *(float2*)&Ps[(r0    )*PAD + col] = make_float2(oacc[j][0]*il_lo, oacc[j][1]*il_lo);
            *(float2*)&Ps[(r0 + 8)*PAD + col] = make_float2(oacc[j][2]*il_hi, oacc[j][3]*il_hi);
        }
    }
    __syncthreads();   // done with Ks/Vs; O staged

    // Load E into Ks region (flat 64x64)
#pragma unroll
    for (int i4 = tid; i4 < 1024; i4 += 128)
        ((float4*)Ks)[i4] = ((const float4*)g_E)[i4];
    __syncthreads();

    // Epilogue: out = O @ E^T + be  (fp32 SIMT). Thread -> row tid/2, col half (tid&1)*32.
    {
        const int r  = tid >> 1;
        const int cb = (tid & 1) * 32;
        float acc[32];
#pragma unroll
        for (int c = 0; c < 32; c++) acc[c] = g_be[cb + c];
        for (int i = 0; i < 64; i++) {
            float xv = Ps[r*PAD + i];
#pragma unroll
            for (int c = 0; c < 32; c++)
                acc[c] += xv * Ks[(cb + c)*64 + i];
        }
        float* ob = out + ((size_t)(b*SEQ + q0 + r))*1024 + h*64 + cb;
#pragma unroll
        for (int c4 = 0; c4 < 8; c4++)
            *(float4*)&ob[c4*4] = make_float4(acc[c4*4], acc[c4*4+1], acc[c4*4+2], acc[c4*4+3]);
    }
}

// ---------------- launch ----------------
extern "C" void kernel_launch(void* const* d_in, const int* in_sizes, int n_in,
                              void* d_out, int out_size)
{
    (void)in_sizes; (void)n_in; (void)out_size;
    const float* x   = (const float*)d_in[0];
    const float* Wi  = (const float*)d_in[1];
    const float* bi  = (const float*)d_in[2];
    const float* Wq  = (const float*)d_in[3];
    const float* bq  = (const float*)d_in[4];
    const float* Wk  = (const float*)d_in[5];
    const float* bk  = (const float*)d_in[6];
    const float* Wv  = (const float*)d_in[7];
    const float* bv  = (const float*)d_in[8];
    const float* Wc  = (const float*)d_in[9];
    const float* bc  = (const float*)d_in[10];
    const float* Wci = (const float*)d_in[11];
    const float* bci = (const float*)d_in[12];
    const float* Wm  = (const float*)d_in[13];
    const float* bm  = (const float*)d_in[14];
    const float* Wmi = (const float*)d_in[15];
    const float* bmi = (const float*)d_in[16];

    const int smem_qkv  = 4 * 64 * PAD * 4;   // 73728 B
    const int smem_attn = 3 * 64 * PAD * 4;   // 55296 B
    cudaFuncSetAttribute(qkv_kernel,  cudaFuncAttributeMaxDynamicSharedMemorySize, smem_qkv);
    cudaFuncSetAttribute(attn_kernel, cudaFuncAttributeMaxDynamicSharedMemorySize, smem_attn);

    precompute_kernel<<<1, 256>>>(Wi, bi, Wq, bq, Wk, bk, Wv, bv,
                                  Wc, bc, Wci, bci, Wm, bm, Wmi, bmi);
    qkv_kernel<<<dim3(32, 64), 128, smem_qkv>>>(x);
    attn_kernel<<<dim3(32, 64), 128, smem_attn>>>((float*)d_out);
}

// round 2
// speedup vs baseline: 3.0704x; 3.0704x over previous
#include <cuda_runtime.h>
#include <cuda_bf16.h>
#include <cstdint>

#define SEQ   2048
#define BATCH 4
#define HEADS 16
#define BH    (BATCH*HEADS)   // 64
#define PADH  72              // bf16 smem row stride: 144B -> conflict-free ldmatrix/LDS

typedef __nv_bfloat16 bf16;

// ---------------- device globals (no allocs allowed) ----------------
__device__ bf16  g_Wqh[4096], g_Wkh[4096], g_Wvh[4096], g_Eh[4096];
__device__ float g_bq[64], g_bk[64], g_bv[64], g_be[64];
__device__ bf16  g_Qh[BH*SEQ*64];
__device__ bf16  g_Kh[BH*SEQ*64];
__device__ bf16  g_Vh[BH*SEQ*64];

// ---------------- helpers ----------------
__device__ __forceinline__ uint32_t packbf(float a, float b) {
    __nv_bfloat162 h = __floats2bfloat162_rn(a, b);   // a -> low, b -> high
    return *reinterpret_cast<uint32_t*>(&h);
}

__device__ __forceinline__ void mma16(float* d, const uint32_t* a, uint32_t b0, uint32_t b1) {
    asm volatile(
        "mma.sync.aligned.m16n8k16.row.col.f32.bf16.bf16.f32 "
        "{%0,%1,%2,%3}, {%4,%5,%6,%7}, {%8,%9}, {%0,%1,%2,%3};"
        : "+f"(d[0]), "+f"(d[1]), "+f"(d[2]), "+f"(d[3])
        : "r"(a[0]), "r"(a[1]), "r"(a[2]), "r"(a[3]), "r"(b0), "r"(b1));
}

__device__ __forceinline__ void ldm4(uint32_t* r, uint32_t addr) {
    asm volatile("ldmatrix.sync.aligned.m8n8.x4.shared.b16 {%0,%1,%2,%3}, [%4];"
        : "=r"(r[0]), "=r"(r[1]), "=r"(r[2]), "=r"(r[3]) : "r"(addr));
}
__device__ __forceinline__ void ldm4t(uint32_t* r, uint32_t addr) {
    asm volatile("ldmatrix.sync.aligned.m8n8.x4.trans.shared.b16 {%0,%1,%2,%3}, [%4];"
        : "=r"(r[0]), "=r"(r[1]), "=r"(r[2]), "=r"(r[3]) : "r"(addr));
}

__device__ __forceinline__ uint32_t sptr(const void* p) {
    return (uint32_t)__cvta_generic_to_shared(p);
}
__device__ __forceinline__ void cp16(uint32_t dst, const void* src) {
    asm volatile("cp.async.ca.shared.global [%0], [%1], 16;" :: "r"(dst), "l"(src));
}
__device__ __forceinline__ void cpcommit() { asm volatile("cp.async.commit_group;"); }
template<int N> __device__ __forceinline__ void cpwait() {
    asm volatile("cp.async.wait_group %0;" :: "n"(N));
}

// ---------------- kernel 1: fuse all weights/biases (5 blocks) ----------------
__global__ void precompute_kernel(
    const float* __restrict__ Wi,  const float* __restrict__ bi,
    const float* __restrict__ Wq,  const float* __restrict__ bq,
    const float* __restrict__ Wk,  const float* __restrict__ bk,
    const float* __restrict__ Wv,  const float* __restrict__ bv,
    const float* __restrict__ Wc,  const float* __restrict__ bc,
    const float* __restrict__ Wci, const float* __restrict__ bci,
    const float* __restrict__ Wm,  const float* __restrict__ bm,
    const float* __restrict__ Wmi, const float* __restrict__ bmi)
{
    const int blk = blockIdx.x, tid = threadIdx.x;
    if (blk < 3) {
        // fused weight: W' = Wx @ Wi  (bf16 out)
        __shared__ float A[4096], B[4096];
        const float* Wx = (blk == 0) ? Wq : (blk == 1) ? Wk : Wv;
        bf16* dst       = (blk == 0) ? g_Wqh : (blk == 1) ? g_Wkh : g_Wvh;
        for (int i = tid; i < 4096; i += 256) { A[i] = Wx[i]; B[i] = Wi[i]; }
        __syncthreads();
        for (int idx = tid; idx < 4096; idx += 256) {
            int o = idx >> 6, i = idx & 63;
            float a = 0.f;
            for (int j = 0; j < 64; j++) a += A[o*64 + j] * B[j*64 + i];
            dst[idx] = __float2bfloat16_rn(a);
        }
    } else if (blk == 3) {
        // fused biases: b' = Wx @ bi + bx
        for (int tt = tid; tt < 192; tt += 256) {
            int mat = tt >> 6, o = tt & 63;
            const float* Wx = (mat == 0) ? Wq : (mat == 1) ? Wk : Wv;
            const float* bx = (mat == 0) ? bq : (mat == 1) ? bk : bv;
            float* dst      = (mat == 0) ? g_bq : (mat == 1) ? g_bk : g_bv;
            float a = bx[o];
            for (int j = 0; j < 64; j++) a += Wx[o*64 + j] * bi[j];
            dst[o] = a;
        }
    } else {
        // E = (Wmi@Wm) @ (Wci@Wc);  be = (Wmi@Wm)@(Wci@bc + bci) + Wmi@bm + bmi
        __shared__ float M1[4096], M2[4096], b1s[64];
        for (int idx = tid; idx < 4096; idx += 256) {
            int o = idx >> 6, i = idx & 63;
            float a1 = 0.f;
            for (int j = 0; j < 8; j++) a1 += Wci[o*8 + j] * Wc[j*64 + i];
            M1[idx] = a1;
            float a2 = 0.f;
            for (int j = 0; j < 4; j++) a2 += Wmi[o*4 + j] * Wm[j*64 + i];
            M2[idx] = a2;
        }
        for (int o = tid; o < 64; o += 256) {
            float a = bci[o];
            for (int j = 0; j < 8; j++) a += Wci[o*8 + j] * bc[j];
            b1s[o] = a;
        }
        __syncthreads();
        for (int idx = tid; idx < 4096; idx += 256) {
            int o = idx >> 6, i = idx & 63;
            float e = 0.f;
            for (int j = 0; j < 64; j++) e += M2[o*64 + j] * M1[j*64 + i];
            g_Eh[idx] = __float2bfloat16_rn(e);
        }
        for (int o = tid; o < 64; o += 256) {
            float a = bmi[o];
            for (int j = 0; j < 4; j++)  a += Wmi[o*4 + j] * bm[j];
            for (int j = 0; j < 64; j++) a += M2[o*64 + j] * b1s[j];
            g_be[o] = a;
        }
    }
}

// ---------------- kernel 2: QKV projection (bf16 mma) ----------------
// grid (16, 64), 256 threads (8 warps x 16 rows = 128 rows/CTA)
__global__ __launch_bounds__(256) void qkv_kernel(const float* __restrict__ x)
{
    __shared__ __align__(16) bf16 xs[128*PADH];     // 18432 B
    __shared__ __align__(16) bf16 ws[3][64*PADH];   // 27648 B

    const int s0 = blockIdx.x * 128;
    const int bh = blockIdx.y;
    const int b  = bh >> 4, h = bh & 15;
    const int tid  = threadIdx.x;
    const int w    = tid >> 5, lane = tid & 31, g = lane >> 2, t = lane & 3;
    const int r0   = w*16 + g;

    // stage x (fp32 -> bf16) : 4096 float2 pairs
    const float* xbase = x + ((size_t)(b*SEQ + s0))*1024 + h*64;
    for (int p = tid; p < 4096; p += 256) {
        int r = p >> 5, c2 = (p & 31) * 2;
        float2 v = *(const float2*)&xbase[(size_t)r*1024 + c2];
        *(uint32_t*)&xs[r*PADH + c2] = packbf(v.x, v.y);
    }
    // stage the three fused weights (bf16 pairs)
    {
        const uint32_t* wsrc[3] = {(const uint32_t*)g_Wqh, (const uint32_t*)g_Wkh, (const uint32_t*)g_Wvh};
        for (int m = 0; m < 3; m++)
            for (int p = tid; p < 2048; p += 256) {
                int r = p >> 5, c2 = (p & 31) * 2;
                *(uint32_t*)&ws[m][r*PADH + c2] = wsrc[m][p];
            }
    }
    __syncthreads();

    // A fragments (x rows) — register resident across all 3 matrices
    uint32_t a[4][4];
#pragma unroll
    for (int kk = 0; kk < 4; kk++) {
        int c0 = 16*kk + 2*t;
        a[kk][0] = *(const uint32_t*)&xs[(r0    )*PADH + c0    ];
        a[kk][1] = *(const uint32_t*)&xs[(r0 + 8)*PADH + c0    ];
        a[kk][2] = *(const uint32_t*)&xs[(r0    )*PADH + c0 + 8];
        a[kk][3] = *(const uint32_t*)&xs[(r0 + 8)*PADH + c0 + 8];
    }

    const float* bias[3] = {g_bq, g_bk, g_bv};
    bf16* outp[3]        = {g_Qh, g_Kh, g_Vh};

    for (int mat = 0; mat < 3; mat++) {
        float acc[8][4];
#pragma unroll
        for (int j = 0; j < 8; j++)
#pragma unroll
            for (int q = 0; q < 4; q++) acc[j][q] = 0.f;

#pragma unroll
        for (int j = 0; j < 8; j++)
#pragma unroll
            for (int kk = 0; kk < 4; kk++) {
                uint32_t b0 = *(const uint32_t*)&ws[mat][(8*j + g)*PADH + 16*kk + 2*t    ];
                uint32_t b1 = *(const uint32_t*)&ws[mat][(8*j + g)*PADH + 16*kk + 2*t + 8];
                mma16(acc[j], a[kk], b0, b1);
            }

        bf16* op = outp[mat];
        const float* bp = bias[mat];
        const float sc = (mat == 0) ? 0.125f : 1.0f;   // fold 1/sqrt(64) into Q
        const size_t base = (size_t)bh*SEQ + s0;
#pragma unroll
        for (int j = 0; j < 8; j++) {
            int col = 8*j + 2*t;
            float bb0 = bp[col], bb1 = bp[col+1];
            *(uint32_t*)&op[(base + r0    )*64 + col] = packbf((acc[j][0]+bb0)*sc, (acc[j][1]+bb1)*sc);
            *(uint32_t*)&op[(base + r0 + 8)*64 + col] = packbf((acc[j][2]+bb0)*sc, (acc[j][3]+bb1)*sc);
        }
    }
}

// ---------------- kernel 3: flash attention + fused epilogue ----------------
// grid (16, 64), 256 threads (8 warps x 16 q-rows = 128 q-rows/CTA), Bc=64
__global__ __launch_bounds__(256) void attn_kernel(float* __restrict__ out)
{
    __shared__ __align__(16) bf16 Ks[2][64*PADH];   // 2 x 9216 B
    __shared__ __align__(16) bf16 Vs[2][64*PADH];   // 2 x 9216 B

    const int q0 = blockIdx.x * 128;
    const int bh = blockIdx.y;
    const int b  = bh >> 4, h = bh & 15;
    const int tid  = threadIdx.x;
    const int w    = tid >> 5, lane = tid & 31, g = lane >> 2, t = lane & 3;
    const int r0   = w*16 + g;

    // Q fragments (pre-scaled by 0.125 in qkv), direct from global
    uint32_t aq[4][4];
    {
        const uint32_t* qp = (const uint32_t*)(g_Qh + ((size_t)bh*SEQ + q0)*64);
#pragma unroll
        for (int kk = 0; kk < 4; kk++) {
            aq[kk][0] = qp[(r0    )*32 + 8*kk + t    ];
            aq[kk][1] = qp[(r0 + 8)*32 + 8*kk + t    ];
            aq[kk][2] = qp[(r0    )*32 + 8*kk + t + 4];
            aq[kk][3] = qp[(r0 + 8)*32 + 8*kk + t + 4];
        }
    }

    float oacc[8][4];
#pragma unroll
    for (int j = 0; j < 8; j++)
#pragma unroll
        for (int q = 0; q < 4; q++) oacc[j][q] = 0.f;
    float m_lo = -1e30f, m_hi = -1e30f, l_lo = 0.f, l_hi = 0.f;

    const bf16* Kg = g_Kh + (size_t)bh*SEQ*64;
    const bf16* Vg = g_Vh + (size_t)bh*SEQ*64;
    const uint32_t ksb[2] = {sptr(Ks[0]), sptr(Ks[1])};
    const uint32_t vsb[2] = {sptr(Vs[0]), sptr(Vs[1])};

    // ldmatrix lane-address components (hoisted)
    const int l7  = lane & 7;          // row within 8x8 tile
    const int lt1 = (lane >> 3) & 1;   // k-half select
    const int lt2 = lane >> 4;         // j select within J-pair

    auto issue_stage = [&](int st, int kt) {
        const bf16* kg = Kg + (size_t)kt*4096;
        const bf16* vg = Vg + (size_t)kt*4096;
#pragma unroll
        for (int c = 0; c < 2; c++) {
            int i = c*256 + tid;                       // 512 chunks of 16B per tile
            uint32_t off = (uint32_t)(((i >> 3)*PADH + (i & 7)*8) * 2);
            cp16(ksb[st] + off, kg + i*8);
            cp16(vsb[st] + off, vg + i*8);
        }
        cpcommit();
    };

    issue_stage(0, 0);

    for (int kt = 0; kt < SEQ/64; kt++) {
        const int st = kt & 1;
        if (kt < SEQ/64 - 1) { issue_stage(st ^ 1, kt + 1); cpwait<1>(); }
        else                 { cpwait<0>(); }
        __syncthreads();

        // ---- S = Q K^T ----
        float s[8][4];
#pragma unroll
        for (int j = 0; j < 8; j++)
#pragma unroll
            for (int q = 0; q < 4; q++) s[j][q] = 0.f;

#pragma unroll
        for (int J = 0; J < 4; J++) {
            uint32_t rowK = (uint32_t)((8*(2*J + lt2) + l7) * (PADH*2));
#pragma unroll
            for (int kk = 0; kk < 4; kk++) {
                uint32_t bk[4];
                ldm4(bk, ksb[st] + rowK + (uint32_t)((16*kk + 8*lt1) * 2));
                mma16(s[2*J    ], aq[kk], bk[0], bk[1]);
                mma16(s[2*J + 1], aq[kk], bk[2], bk[3]);
            }
        }

        // ---- online softmax (rows r0, r0+8; quad reduction) ----
        float tmx_lo = -1e30f, tmx_hi = -1e30f;
#pragma unroll
        for (int j = 0; j < 8; j++) {
            tmx_lo = fmaxf(tmx_lo, fmaxf(s[j][0], s[j][1]));
            tmx_hi = fmaxf(tmx_hi, fmaxf(s[j][2], s[j][3]));
        }
#pragma unroll
        for (int off = 1; off < 4; off <<= 1) {
            tmx_lo = fmaxf(tmx_lo, __shfl_xor_sync(0xffffffffu, tmx_lo, off));
            tmx_hi = fmaxf(tmx_hi, __shfl_xor_sync(0xffffffffu, tmx_hi, off));
        }
        float mn_lo = fmaxf(m_lo, tmx_lo), mn_hi = fmaxf(m_hi, tmx_hi);
        float sc_lo = __expf(m_lo - mn_lo), sc_hi = __expf(m_hi - mn_hi);
        m_lo = mn_lo; m_hi = mn_hi;

        float rs_lo = 0.f, rs_hi = 0.f;
#pragma unroll
        for (int j = 0; j < 8; j++) {
            s[j][0] = __expf(s[j][0] - mn_lo);
            s[j][1] = __expf(s[j][1] - mn_lo);
            s[j][2] = __expf(s[j][2] - mn_hi);
            s[j][3] = __expf(s[j][3] - mn_hi);
            rs_lo += s[j][0] + s[j][1];
            rs_hi += s[j][2] + s[j][3];
        }
#pragma unroll
        for (int off = 1; off < 4; off <<= 1) {
            rs_lo += __shfl_xor_sync(0xffffffffu, rs_lo, off);
            rs_hi += __shfl_xor_sync(0xffffffffu, rs_hi, off);
        }
        l_lo = l_lo * sc_lo + rs_lo;
        l_hi = l_hi * sc_hi + rs_hi;
#pragma unroll
        for (int j = 0; j < 8; j++) {
            oacc[j][0] *= sc_lo; oacc[j][1] *= sc_lo;
            oacc[j][2] *= sc_hi; oacc[j][3] *= sc_hi;
        }

        // ---- pack P: C-fragment layout == A-fragment layout (no smem) ----
        uint32_t pa[4][4];
#pragma unroll
        for (int kk = 0; kk < 4; kk++) {
            pa[kk][0] = packbf(s[2*kk    ][0], s[2*kk    ][1]);
            pa[kk][1] = packbf(s[2*kk    ][2], s[2*kk    ][3]);
            pa[kk][2] = packbf(s[2*kk + 1][0], s[2*kk + 1][1]);
            pa[kk][3] = packbf(s[2*kk + 1][2], s[2*kk + 1][3]);
        }

        // ---- O += P V (trans-ldmatrix B from row-major V) ----
#pragma unroll
        for (int J = 0; J < 4; J++) {
            uint32_t colV = (uint32_t)(8*(2*J + lt2) * 2);
#pragma unroll
            for (int kk = 0; kk < 4; kk++) {
                uint32_t bv[4];
                ldm4t(bv, vsb[st] + (uint32_t)((16*kk + 8*lt1 + l7) * (PADH*2)) + colV);
                mma16(oacc[2*J    ], pa[kk], bv[0], bv[1]);
                mma16(oacc[2*J + 1], pa[kk], bv[2], bv[3]);
            }
        }
        __syncthreads();
    }

    // ---- normalize + pack O as A-fragments ----
    float il_lo = 1.f / l_lo, il_hi = 1.f / l_hi;
    uint32_t ea[4][4];
#pragma unroll
    for (int kk = 0; kk < 4; kk++) {
        ea[kk][0] = packbf(oacc[2*kk    ][0]*il_lo, oacc[2*kk    ][1]*il_lo);
        ea[kk][1] = packbf(oacc[2*kk    ][2]*il_hi, oacc[2*kk    ][3]*il_hi);
        ea[kk][2] = packbf(oacc[2*kk + 1][0]*il_lo, oacc[2*kk + 1][1]*il_lo);
        ea[kk][3] = packbf(oacc[2*kk + 1][2]*il_hi, oacc[2*kk + 1][3]*il_hi);
    }

    // ---- load E (reuse Ks[0]) ----
    bf16* Es = &Ks[0][0];
    for (int p = tid; p < 2048; p += 256) {
        int r = p >> 5, c2 = (p & 31) * 2;
        *(uint32_t*)&Es[r*PADH + c2] = ((const uint32_t*)g_Eh)[p];
    }
    __syncthreads();

    // ---- epilogue: out = O E^T + be (bf16 mma) ----
    float e[8][4];
#pragma unroll
    for (int j = 0; j < 8; j++)
#pragma unroll
        for (int q = 0; q < 4; q++) e[j][q] = 0.f;
#pragma unroll
    for (int j = 0; j < 8; j++)
#pragma unroll
        for (int kk = 0; kk < 4; kk++) {
            uint32_t b0 = *(const uint32_t*)&Es[(8*j + g)*PADH + 16*kk + 2*t    ];
            uint32_t b1 = *(const uint32_t*)&Es[(8*j + g)*PADH + 16*kk + 2*t + 8];
            mma16(e[j], ea[kk], b0, b1);
        }

    float* ob = out + ((size_t)(b*SEQ + q0))*1024 + h*64;
#pragma unroll
    for (int j = 0; j < 8; j++) {
        int col = 8*j + 2*t;
        float b0 = __ldg(&g_be[col]), b1 = __ldg(&g_be[col + 1]);
        *(float2*)&ob[(size_t)(r0    )*1024 + col] = make_float2(e[j][0] + b0, e[j][1] + b1);
        *(float2*)&ob[(size_t)(r0 + 8)*1024 + col] = make_float2(e[j][2] + b0, e[j][3] + b1);
    }
}

// ---------------- launch ----------------
extern "C" void kernel_launch(void* const* d_in, const int* in_sizes, int n_in,
                              void* d_out, int out_size)
{
    (void)in_sizes; (void)n_in; (void)out_size;
    const float* x   = (const float*)d_in[0];
    const float* Wi  = (const float*)d_in[1];
    const float* bi  = (const float*)d_in[2];
    const float* Wq  = (const float*)d_in[3];
    const float* bq  = (const float*)d_in[4];
    const float* Wk  = (const float*)d_in[5];
    const float* bk  = (const float*)d_in[6];
    const float* Wv  = (const float*)d_in[7];
    const float* bv  = (const float*)d_in[8];
    const float* Wc  = (const float*)d_in[9];
    const float* bc  = (const float*)d_in[10];
    const float* Wci = (const float*)d_in[11];
    const float* bci = (const float*)d_in[12];
    const float* Wm  = (const float*)d_in[13];
    const float* bm  = (const float*)d_in[14];
    const float* Wmi = (const float*)d_in[15];
    const float* bmi = (const float*)d_in[16];

    precompute_kernel<<<5, 256>>>(Wi, bi, Wq, bq, Wk, bk, Wv, bv,
                                  Wc, bc, Wci, bci, Wm, bm, Wmi, bmi);
    qkv_kernel<<<dim3(16, 64), 256>>>(x);
    attn_kernel<<<dim3(16, 64), 256>>>((float*)d_out);
}